// round 12
// baseline (speedup 1.0000x reference)
#include <cuda_runtime.h>
#include <cstdint>

// HGN forward. Shapes fixed: U=I=100000, D=64, L=50, B=4096, T=100.
#define D 64
#define LSEQ 50
#define TPRED 100
#define PRE_BPB 4
#define BMAX 4096
#define SUBMAX 13

typedef unsigned long long u64;

__device__ float g_ubias[BMAX * D];    // u@fg_user_W + fub + fib
__device__ float g_ugu[BMAX * LSEQ];   // u@instance_gate_user

static __device__ __forceinline__ u64 pk(float a, float b) {
    u64 r;
    asm("mov.b64 %0, {%1, %2};" : "=l"(r) : "f"(a), "f"(b));
    return r;
}
static __device__ __forceinline__ void upk(u64 v, float& a, float& b) {
    asm("mov.b64 {%0, %1}, %2;" : "=f"(a), "=f"(b) : "l"(v));
}
static __device__ __forceinline__ u64 fma2(u64 a, u64 b, u64 c) {
    u64 r;
    asm("fma.rn.f32x2 %0, %1, %2, %3;" : "=l"(r) : "l"(a), "l"(b), "l"(c));
    return r;
}
static __device__ __forceinline__ u64 add2(u64 a, u64 b) {
    u64 r;
    asm("add.rn.f32x2 %0, %1, %2;" : "=l"(r) : "l"(a), "l"(b));
    return r;
}
static __device__ __forceinline__ float sigmoidf(float x) {
    return 1.0f / (1.0f + __expf(-x));
}

// ---------------------------------------------------------------------------
// Precompute: g_ubias[b][d] = u@fg_user_W + fub + fib ; g_ugu[b][l] = u@gu
// ---------------------------------------------------------------------------
__global__ __launch_bounds__(128) void hgn_pre(
    const int* __restrict__ user_ids, const float* __restrict__ user_tab,
    const float* __restrict__ fuW, const float* __restrict__ fub,
    const float* __restrict__ fib, const float* __restrict__ gu, int B)
{
    __shared__ __align__(16) float s_u[D];
    const int j = threadIdx.x;
    float wcol[D];
    float biasj = 0.0f;
    if (j < D) {
        #pragma unroll
        for (int k = 0; k < D; k++) wcol[k] = fuW[k * D + j];
        biasj = fub[j] + fib[j];
    } else if (j < D + LSEQ) {
        const int jj = j - D;
        #pragma unroll
        for (int k = 0; k < D; k++) wcol[k] = gu[k * LSEQ + jj];
    }
    const int b0 = blockIdx.x * PRE_BPB;
    for (int bb = 0; bb < PRE_BPB; bb++) {
        const int b = b0 + bb;
        if (b >= B) break;
        if (j < D) s_u[j] = user_tab[(size_t)user_ids[b] * D + j];
        __syncthreads();
        float acc = biasj;
        const float4* up = (const float4*)s_u;
        #pragma unroll
        for (int q = 0; q < D / 4; q++) {
            float4 r = up[q];
            acc += r.x * wcol[4*q] + r.y * wcol[4*q+1] + r.z * wcol[4*q+2] + r.w * wcol[4*q+3];
        }
        if (j < D)             g_ubias[b * D + j] = acc;
        else if (j < D + LSEQ) g_ugu[b * LSEQ + (j - D)] = acc;
        __syncthreads();
    }
}

// ---------------------------------------------------------------------------
// Main kernel: one batch per 128-thread block.
// Thread = (K-half g = tid>>6, output column d = tid&63).
// Weights pre-packed as consecutive-k pairs (W[k][d], W[k+1][d]) so the item
// operand pair (item[k], item[k+1]) comes straight from aligned LDS.128 —
// no scalar-duplication MOVs. Accumulator = (even-k, odd-k) partial for d,
// folded once at combine. Gated values overwrite s_item in NATURAL layout.
// Instance dot: per-warp half-row reduce in combine -> s_scp -> tiny fold.
// ---------------------------------------------------------------------------
__global__ __launch_bounds__(128, 8) void hgn_main(
    const int* __restrict__ item_seq,
    const int* __restrict__ user_ids,
    const int* __restrict__ items_pred,
    const float* __restrict__ user_tab,
    const float* __restrict__ item_tab,
    const float* __restrict__ fiW,
    const float* __restrict__ gi,
    const float* __restrict__ W2,
    const float* __restrict__ b2,
    float* __restrict__ out,
    int B)
{
    __shared__ __align__(16) float s_item[LSEQ][D];   // items -> gated (natural, in place)
    __shared__ __align__(16) u64 s_p[2][SUBMAX][D];   // K-half partials (packed even/odd)
    __shared__ __align__(16) float s_isum[2][D];      // per-parity item sums
    __shared__ __align__(16) float s_v[D];
    __shared__ float s_scp[LSEQ][2];                  // per-warp-half instance dots
    __shared__ float s_score[LSEQ];
    __shared__ int s_idx[TPRED];

    const int tid  = threadIdx.x;
    const int lane = tid & 31;
    const int w    = tid >> 5;
    const int g    = tid >> 6;        // K-half
    const int d    = tid & 63;        // output column
    const int b    = blockIdx.x;
    if (b >= B) return;

    // Packed weight pairs: wcol[j] = (fiW[32g+2j][d], fiW[32g+2j+1][d])
    u64 wcol[16];
    #pragma unroll
    for (int j = 0; j < 16; j++) {
        wcol[j] = pk(fiW[(32 * g + 2 * j) * D + d],
                     fiW[(32 * g + 2 * j + 1) * D + d]);
    }
    const float gi_d = gi[d];
    const float bias_d = g_ubias[b * D + d];
    const float uemb = (tid < D) ? user_tab[(size_t)user_ids[b] * D + tid] : 0.0f;

    // --- gather item rows (16 threads share one seq index -> LDG bcast);
    //     stage prediction indices in the same phase ---
    #pragma unroll
    for (int i = 0; i < 7; i++) {
        const int idx = tid + 128 * i;
        if (idx < LSEQ * 16) {
            const int rl = idx >> 4, q = idx & 15;
            const int it = __ldg(&item_seq[(size_t)b * LSEQ + rl]);
            ((float4*)s_item[rl])[q] =
                ((const float4*)(item_tab + (size_t)it * D))[q];
        }
    }
    if (tid < TPRED) s_idx[tid] = items_pred[(size_t)b * TPRED + tid];
    __syncthreads();

    // --- gating GEMM + combine, 4 row subtiles ---
    const int SUB0[5] = {0, 13, 26, 38, 50};
    const u64 Z = pk(0.f, 0.f);
    float isum_f = 0.0f;
    const int halfsel = w & 1;        // which 32-d half this warp covers
    #pragma unroll
    for (int s = 0; s < 4; s++) {
        const int l0 = SUB0[s], l1 = SUB0[s + 1];
        const int nr = l1 - l0;
        // GEMM: this thread's K-half for all subtile rows, 2 rows at a time
        int li = 0;
        for (; li + 1 < nr; li += 2) {
            const ulonglong2* r0 = (const ulonglong2*)&s_item[l0 + li][32 * g];
            const ulonglong2* r1 = (const ulonglong2*)&s_item[l0 + li + 1][32 * g];
            u64 a0 = Z, a1 = Z, c0 = Z, c1 = Z;
            #pragma unroll
            for (int q = 0; q < 8; q += 2) {
                const ulonglong2 x0 = r0[q];
                a0 = fma2(x0.x, wcol[2*q+0], a0);
                a1 = fma2(x0.y, wcol[2*q+1], a1);
                const ulonglong2 x1 = r0[q + 1];
                a0 = fma2(x1.x, wcol[2*q+2], a0);
                a1 = fma2(x1.y, wcol[2*q+3], a1);
                const ulonglong2 y0 = r1[q];
                c0 = fma2(y0.x, wcol[2*q+0], c0);
                c1 = fma2(y0.y, wcol[2*q+1], c1);
                const ulonglong2 y1 = r1[q + 1];
                c0 = fma2(y1.x, wcol[2*q+2], c0);
                c1 = fma2(y1.y, wcol[2*q+3], c1);
            }
            s_p[g][li][d]     = add2(a0, a1);
            s_p[g][li + 1][d] = add2(c0, c1);
        }
        if (li < nr) {
            const ulonglong2* r0 = (const ulonglong2*)&s_item[l0 + li][32 * g];
            u64 a0 = Z, a1 = Z;
            #pragma unroll
            for (int q = 0; q < 8; q++) {
                const ulonglong2 x = r0[q];
                a0 = fma2(x.x, wcol[2*q+0], a0);
                a1 = fma2(x.y, wcol[2*q+1], a1);
            }
            s_p[g][li][d] = add2(a0, a1);
        }
        __syncthreads();
        // combine + gate: rows of parity g; thread covers its own column d.
        for (int lc = g; lc < nr; lc += 2) {
            const int l = l0 + lc;
            const float itm = s_item[l][d];
            const u64 pu = add2(s_p[0][lc][d], s_p[1][lc][d]);
            float plo, phi;
            upk(pu, plo, phi);
            const float gated = itm * sigmoidf(plo + phi + bias_d);
            isum_f += itm;
            // instance-gate half-dot over this warp's 32 columns
            float gp = gated * gi_d;
            gp += __shfl_xor_sync(0xffffffffu, gp, 16);
            gp += __shfl_xor_sync(0xffffffffu, gp, 8);
            gp += __shfl_xor_sync(0xffffffffu, gp, 4);
            gp += __shfl_xor_sync(0xffffffffu, gp, 2);
            gp += __shfl_xor_sync(0xffffffffu, gp, 1);
            if (lane == 0) s_scp[l][halfsel] = gp;
            s_item[l][d] = gated;
        }
        __syncthreads();
    }
    s_isum[g][d] = isum_f;

    // --- prefetch scoring iter 0 into regs (covers fold+union latency) ---
    const int g4 = lane >> 3;
    const int gl = lane & 7;
    const int t0 = w * 4 + g4;
    const int it0 = s_idx[t0];
    const float4* row0 = (const float4*)(W2 + (size_t)it0 * D);
    const float4 pa = row0[gl * 2];
    const float4 pc = row0[gl * 2 + 1];
    const float pb2 = b2[it0];

    // --- fold instance-score halves ---
    if (tid < LSEQ)
        s_score[tid] = sigmoidf(s_scp[tid][0] + s_scp[tid][1]
                                + g_ugu[b * LSEQ + tid]);
    __syncthreads();

    // --- union + v (64 threads; natural layout) ---
    if (tid < D) {
        float ssum = 0.0f, uo = 0.0f;
        #pragma unroll 5
        for (int l = 0; l < LSEQ; l++) {
            const float sc = s_score[l];
            ssum += sc;
            uo += s_item[l][tid] * sc;
        }
        s_v[tid] = uemb + s_isum[0][tid] + s_isum[1][tid] + uo / ssum;
    }
    __syncthreads();

    // --- scoring: 4 warps x 4 outputs/iter over 100 outputs ---
    {
        const float4 va = *(const float4*)&s_v[gl * 8];
        const float4 vb = *(const float4*)&s_v[gl * 8 + 4];
        float* outp = out + (size_t)b * TPRED;
        // iter 0 from prefetched registers
        {
            float p = pa.x * va.x + pa.y * va.y + pa.z * va.z + pa.w * va.w
                    + pc.x * vb.x + pc.y * vb.y + pc.z * vb.z + pc.w * vb.w;
            p += __shfl_xor_sync(0xffffffffu, p, 1);
            p += __shfl_xor_sync(0xffffffffu, p, 2);
            p += __shfl_xor_sync(0xffffffffu, p, 4);
            if (gl == 0) outp[t0] = p + pb2;
        }
        #pragma unroll
        for (int i = 1; i < 7; i++) {
            const int t = w * 4 + g4 + 16 * i;
            const int tt = (t < TPRED) ? t : 0;
            const int it = s_idx[tt];
            const float4* rowp = (const float4*)(W2 + (size_t)it * D);
            const float4 a = rowp[gl * 2];
            const float4 c = rowp[gl * 2 + 1];
            float p = a.x * va.x + a.y * va.y + a.z * va.z + a.w * va.w
                    + c.x * vb.x + c.y * vb.y + c.z * vb.z + c.w * vb.w;
            p += __shfl_xor_sync(0xffffffffu, p, 1);
            p += __shfl_xor_sync(0xffffffffu, p, 2);
            p += __shfl_xor_sync(0xffffffffu, p, 4);
            if (t < TPRED && gl == 0) outp[t] = p + b2[it];
        }
    }
}

// ---------------------------------------------------------------------------
// Harness entry. Inputs (metadata order):
//  0 item_seq[B,L] i32   1 user_ids[B] i32      2 items_to_predict[B,T] i32
//  3 user_emb[U,D] f32   4 item_emb[I,D] f32
//  5 fg_item_W[D,D]      6 fg_item_b[D]         7 fg_user_W[D,D]   8 fg_user_b[D]
//  9 instance_gate_item[D,1]  10 instance_gate_user[D,L]
// 11 W2_table[I,D]      12 b2_table[I,1]
// Output: res[B,T] f32
// ---------------------------------------------------------------------------
extern "C" void kernel_launch(void* const* d_in, const int* in_sizes, int n_in,
                              void* d_out, int out_size)
{
    const int*   item_seq   = (const int*)d_in[0];
    const int*   user_ids   = (const int*)d_in[1];
    const int*   items_pred = (const int*)d_in[2];
    const float* user_tab   = (const float*)d_in[3];
    const float* item_tab   = (const float*)d_in[4];
    const float* fiW        = (const float*)d_in[5];
    const float* fib        = (const float*)d_in[6];
    const float* fuW        = (const float*)d_in[7];
    const float* fub        = (const float*)d_in[8];
    const float* gi         = (const float*)d_in[9];
    const float* gu         = (const float*)d_in[10];
    const float* W2         = (const float*)d_in[11];
    const float* b2         = (const float*)d_in[12];
    float*       out        = (float*)d_out;

    const int B = in_sizes[1];

    const int pre_grid = (B + PRE_BPB - 1) / PRE_BPB;

    hgn_pre<<<pre_grid, 128>>>(user_ids, user_tab, fuW, fub, fib, gu, B);
    hgn_main<<<B, 128>>>(item_seq, user_ids, items_pred,
                         user_tab, item_tab, fiW, gi, W2, b2, out, B);
}

// round 13
// speedup vs baseline: 1.0395x; 1.0395x over previous
#include <cuda_runtime.h>
#include <cstdint>

// HGN forward. Shapes fixed: U=I=100000, D=64, L=50, B=4096, T=100.
#define D 64
#define LSEQ 50
#define TPRED 100
#define PRE_BPB 4
#define BMAX 4096
#define SUBMAX 13

typedef unsigned long long u64;

__device__ float g_ubias[BMAX * D];    // u@fg_user_W + fub + fib
__device__ float g_ugu[BMAX * LSEQ];   // u@instance_gate_user

static __device__ __forceinline__ u64 pk(float a, float b) {
    u64 r;
    asm("mov.b64 %0, {%1, %2};" : "=l"(r) : "f"(a), "f"(b));
    return r;
}
static __device__ __forceinline__ void upk(u64 v, float& a, float& b) {
    asm("mov.b64 {%0, %1}, %2;" : "=f"(a), "=f"(b) : "l"(v));
}
static __device__ __forceinline__ u64 fma2(u64 a, u64 b, u64 c) {
    u64 r;
    asm("fma.rn.f32x2 %0, %1, %2, %3;" : "=l"(r) : "l"(a), "l"(b), "l"(c));
    return r;
}
static __device__ __forceinline__ u64 add2(u64 a, u64 b) {
    u64 r;
    asm("add.rn.f32x2 %0, %1, %2;" : "=l"(r) : "l"(a), "l"(b));
    return r;
}
static __device__ __forceinline__ float sigmoidf(float x) {
    return 1.0f / (1.0f + __expf(-x));
}

// ---------------------------------------------------------------------------
// Precompute: g_ubias[b][d] = u@fg_user_W + fub + fib ; g_ugu[b][l] = u@gu
// ---------------------------------------------------------------------------
__global__ __launch_bounds__(128) void hgn_pre(
    const int* __restrict__ user_ids, const float* __restrict__ user_tab,
    const float* __restrict__ fuW, const float* __restrict__ fub,
    const float* __restrict__ fib, const float* __restrict__ gu, int B)
{
    __shared__ __align__(16) float s_u[D];
    const int j = threadIdx.x;
    float wcol[D];
    float biasj = 0.0f;
    if (j < D) {
        #pragma unroll
        for (int k = 0; k < D; k++) wcol[k] = fuW[k * D + j];
        biasj = fub[j] + fib[j];
    } else if (j < D + LSEQ) {
        const int jj = j - D;
        #pragma unroll
        for (int k = 0; k < D; k++) wcol[k] = gu[k * LSEQ + jj];
    }
    const int b0 = blockIdx.x * PRE_BPB;
    for (int bb = 0; bb < PRE_BPB; bb++) {
        const int b = b0 + bb;
        if (b >= B) break;
        if (j < D) s_u[j] = user_tab[(size_t)user_ids[b] * D + j];
        __syncthreads();
        float acc = biasj;
        const float4* up = (const float4*)s_u;
        #pragma unroll
        for (int q = 0; q < D / 4; q++) {
            float4 r = up[q];
            acc += r.x * wcol[4*q] + r.y * wcol[4*q+1] + r.z * wcol[4*q+2] + r.w * wcol[4*q+3];
        }
        if (j < D)             g_ubias[b * D + j] = acc;
        else if (j < D + LSEQ) g_ugu[b * LSEQ + (j - D)] = acc;
        __syncthreads();
    }
}

// ---------------------------------------------------------------------------
// Main kernel: one batch per 128-thread block, 4 warps = 4 K-quarters.
// Lane owns columns (lane, lane+32). Weights packed as consecutive-k PAIRS
// per column (wA for lane, wB for lane+32), so the item operand (x[k],x[k+1])
// is directly a u64 half of the broadcast LDS.128 — no duplication MOVs.
// Partials are folded to R9's packed (sumA,sumB) format before STS, so the
// combine / instance-score / union / scoring phases are identical to R9.
// ---------------------------------------------------------------------------
__global__ __launch_bounds__(128, 8) void hgn_main(
    const int* __restrict__ item_seq,
    const int* __restrict__ user_ids,
    const int* __restrict__ items_pred,
    const float* __restrict__ user_tab,
    const float* __restrict__ item_tab,
    const float* __restrict__ fiW,
    const float* __restrict__ gi,
    const float* __restrict__ W2,
    const float* __restrict__ b2,
    float* __restrict__ out,
    int B)
{
    __shared__ __align__(16) float s_item[LSEQ][D];     // items -> gated (packed, in place)
    __shared__ __align__(16) u64 s_pp[4][SUBMAX][32];   // per-warp packed partials
    __shared__ __align__(16) u64 s_isump[4][32];        // per-warp packed item sums
    __shared__ __align__(16) float s_v[D];
    __shared__ float s_score[LSEQ];
    __shared__ int s_idx[TPRED];

    const int tid  = threadIdx.x;
    const int lane = tid & 31;
    const int w    = tid >> 5;       // warp = K-quarter
    const int b    = blockIdx.x;
    if (b >= B) return;

    // Weight pairs for this warp's K-quarter:
    //   wA[j] = (fiW[16w+2j][lane],    fiW[16w+2j+1][lane])
    //   wB[j] = (fiW[16w+2j][lane+32], fiW[16w+2j+1][lane+32])
    u64 wA[8], wB[8];
    #pragma unroll
    for (int j = 0; j < 8; j++) {
        const int k0 = (16 * w + 2 * j) * D;
        const int k1 = (16 * w + 2 * j + 1) * D;
        wA[j] = pk(fiW[k0 + lane],      fiW[k1 + lane]);
        wB[j] = pk(fiW[k0 + lane + 32], fiW[k1 + lane + 32]);
    }
    const float gi_lo = gi[lane];
    const float gi_hi = gi[lane + 32];

    // --- gather item rows (16 threads share one seq index -> LDG bcast);
    //     stage prediction indices in the same phase ---
    #pragma unroll
    for (int i = 0; i < 7; i++) {
        const int idx = tid + 128 * i;
        if (idx < LSEQ * 16) {
            const int rl = idx >> 4, q = idx & 15;
            const int it = __ldg(&item_seq[(size_t)b * LSEQ + rl]);
            ((float4*)s_item[rl])[q] =
                ((const float4*)(item_tab + (size_t)it * D))[q];
        }
    }
    if (tid < TPRED) s_idx[tid] = items_pred[(size_t)b * TPRED + tid];
    const float biasA = g_ubias[b * D + lane];
    const float biasB = g_ubias[b * D + lane + 32];
    const float uemb  = (tid < D) ? user_tab[(size_t)user_ids[b] * D + tid] : 0.0f;
    __syncthreads();

    // --- gating GEMM + fused combine/instance-score, 4 row subtiles ---
    const int SUB0[5] = {0, 13, 26, 38, 50};
    const u64 Z = pk(0.f, 0.f);
    u64 isum2 = Z;
    #pragma unroll
    for (int s = 0; s < 4; s++) {
        const int l0 = SUB0[s], l1 = SUB0[s + 1];
        int l = l0;
        for (; l + 1 < l1; l += 2) {
            u64 aA = Z, aB = Z, cA = Z, cB = Z;
            const ulonglong2* r0 = (const ulonglong2*)&s_item[l][16 * w];
            const ulonglong2* r1 = (const ulonglong2*)&s_item[l + 1][16 * w];
            #pragma unroll
            for (int q = 0; q < 4; q++) {
                const ulonglong2 x = r0[q];           // k-pairs (4q,4q+1),(4q+2,4q+3)
                aA = fma2(x.x, wA[2*q+0], aA);
                aB = fma2(x.x, wB[2*q+0], aB);
                aA = fma2(x.y, wA[2*q+1], aA);
                aB = fma2(x.y, wB[2*q+1], aB);
                const ulonglong2 y = r1[q];
                cA = fma2(y.x, wA[2*q+0], cA);
                cB = fma2(y.x, wB[2*q+0], cB);
                cA = fma2(y.y, wA[2*q+1], cA);
                cB = fma2(y.y, wB[2*q+1], cB);
            }
            float a0, a1, b0, b1, c0, c1, d0, d1;
            upk(aA, a0, a1); upk(aB, b0, b1);
            upk(cA, c0, c1); upk(cB, d0, d1);
            s_pp[w][l - l0][lane]     = pk(a0 + a1, b0 + b1);
            s_pp[w][l + 1 - l0][lane] = pk(c0 + c1, d0 + d1);
        }
        if (l < l1) {
            u64 aA = Z, aB = Z;
            const ulonglong2* r0 = (const ulonglong2*)&s_item[l][16 * w];
            #pragma unroll
            for (int q = 0; q < 4; q++) {
                const ulonglong2 x = r0[q];
                aA = fma2(x.x, wA[2*q+0], aA);
                aB = fma2(x.x, wB[2*q+0], aB);
                aA = fma2(x.y, wA[2*q+1], aA);
                aB = fma2(x.y, wB[2*q+1], aB);
            }
            float a0, a1, b0, b1;
            upk(aA, a0, a1); upk(aB, b0, b1);
            s_pp[w][l - l0][lane] = pk(a0 + a1, b0 + b1);
        }
        __syncthreads();
        // combine + gate + instance score, rows strided over warps (R9 exact).
        for (int lc = l0 + w; lc < l1; lc += 4) {
            const float ug = g_ugu[b * LSEQ + lc];
            const float itA = s_item[lc][lane];
            const float itB = s_item[lc][lane + 32];
            const u64 p = add2(add2(s_pp[0][lc - l0][lane], s_pp[1][lc - l0][lane]),
                               add2(s_pp[2][lc - l0][lane], s_pp[3][lc - l0][lane]));
            float pA, pB;
            upk(p, pA, pB);
            const float gA = itA * sigmoidf(pA + biasA);
            const float gB = itB * sigmoidf(pB + biasB);
            isum2 = add2(isum2, pk(itA, itB));
            float sp = gA * gi_lo + gB * gi_hi;
            sp += __shfl_xor_sync(0xffffffffu, sp, 16);
            sp += __shfl_xor_sync(0xffffffffu, sp, 8);
            sp += __shfl_xor_sync(0xffffffffu, sp, 4);
            sp += __shfl_xor_sync(0xffffffffu, sp, 2);
            sp += __shfl_xor_sync(0xffffffffu, sp, 1);
            if (lane == 0) s_score[lc] = sigmoidf(sp + ug);
            ((float2*)s_item[lc])[lane] = make_float2(gA, gB);
        }
        __syncthreads();
    }
    s_isump[w][lane] = isum2;

    // --- prefetch scoring iter 0 (covers union latency) ---
    const int g4 = lane >> 3;
    const int gl = lane & 7;
    const int t0 = w * 4 + g4;
    const int it0 = s_idx[t0];
    const float4* row0 = (const float4*)(W2 + (size_t)it0 * D);
    const float4 pa = row0[gl * 2];
    const float4 pc = row0[gl * 2 + 1];
    const float pb2 = b2[it0];

    // --- union + v (64 threads) ---
    if (tid < D) {
        const int j = tid & 31, half = tid >> 5;
        float ssum = 0.0f, uo = 0.0f;
        #pragma unroll 5
        for (int l = 0; l < LSEQ; l++) {
            const float sc = s_score[l];
            ssum += sc;
            uo += s_item[l][2 * j + half] * sc;
        }
        const u64 is4 = add2(add2(s_isump[0][j], s_isump[1][j]),
                             add2(s_isump[2][j], s_isump[3][j]));
        float isA, isB;
        upk(is4, isA, isB);
        s_v[tid] = uemb + (half ? isB : isA) + uo / ssum;
    }
    __syncthreads();

    // --- scoring: 4 warps x 4 outputs/iter over 100 outputs ---
    {
        const float4 va = *(const float4*)&s_v[gl * 8];
        const float4 vb = *(const float4*)&s_v[gl * 8 + 4];
        float* outp = out + (size_t)b * TPRED;
        // iter 0 from prefetched registers
        {
            float p = pa.x * va.x + pa.y * va.y + pa.z * va.z + pa.w * va.w
                    + pc.x * vb.x + pc.y * vb.y + pc.z * vb.z + pc.w * vb.w;
            p += __shfl_xor_sync(0xffffffffu, p, 1);
            p += __shfl_xor_sync(0xffffffffu, p, 2);
            p += __shfl_xor_sync(0xffffffffu, p, 4);
            if (gl == 0) outp[t0] = p + pb2;
        }
        #pragma unroll
        for (int i = 1; i < 7; i++) {
            const int t = w * 4 + g4 + 16 * i;
            const int tt = (t < TPRED) ? t : 0;
            const int it = s_idx[tt];
            const float4* rowp = (const float4*)(W2 + (size_t)it * D);
            const float4 a = rowp[gl * 2];
            const float4 c = rowp[gl * 2 + 1];
            float p = a.x * va.x + a.y * va.y + a.z * va.z + a.w * va.w
                    + c.x * vb.x + c.y * vb.y + c.z * vb.z + c.w * vb.w;
            p += __shfl_xor_sync(0xffffffffu, p, 1);
            p += __shfl_xor_sync(0xffffffffu, p, 2);
            p += __shfl_xor_sync(0xffffffffu, p, 4);
            if (t < TPRED && gl == 0) outp[t] = p + b2[it];
        }
    }
}

// ---------------------------------------------------------------------------
// Harness entry. Inputs (metadata order):
//  0 item_seq[B,L] i32   1 user_ids[B] i32      2 items_to_predict[B,T] i32
//  3 user_emb[U,D] f32   4 item_emb[I,D] f32
//  5 fg_item_W[D,D]      6 fg_item_b[D]         7 fg_user_W[D,D]   8 fg_user_b[D]
//  9 instance_gate_item[D,1]  10 instance_gate_user[D,L]
// 11 W2_table[I,D]      12 b2_table[I,1]
// Output: res[B,T] f32
// ---------------------------------------------------------------------------
extern "C" void kernel_launch(void* const* d_in, const int* in_sizes, int n_in,
                              void* d_out, int out_size)
{
    const int*   item_seq   = (const int*)d_in[0];
    const int*   user_ids   = (const int*)d_in[1];
    const int*   items_pred = (const int*)d_in[2];
    const float* user_tab   = (const float*)d_in[3];
    const float* item_tab   = (const float*)d_in[4];
    const float* fiW        = (const float*)d_in[5];
    const float* fib        = (const float*)d_in[6];
    const float* fuW        = (const float*)d_in[7];
    const float* fub        = (const float*)d_in[8];
    const float* gi         = (const float*)d_in[9];
    const float* gu         = (const float*)d_in[10];
    const float* W2         = (const float*)d_in[11];
    const float* b2         = (const float*)d_in[12];
    float*       out        = (float*)d_out;

    const int B = in_sizes[1];

    const int pre_grid = (B + PRE_BPB - 1) / PRE_BPB;

    hgn_pre<<<pre_grid, 128>>>(user_ids, user_tab, fuW, fub, fib, gu, B);
    hgn_main<<<B, 128>>>(item_seq, user_ids, items_pred,
                         user_tab, item_tab, fiW, gi, W2, b2, out, B);
}

// round 14
// speedup vs baseline: 1.0580x; 1.0178x over previous
#include <cuda_runtime.h>
#include <cstdint>

// HGN forward. Shapes fixed: U=I=100000, D=64, L=50, B=4096, T=100.
#define D 64
#define LSEQ 50
#define TPRED 100
#define PRE_BPB 4
#define BMAX 4096
#define SUBMAX 9

typedef unsigned long long u64;

__device__ float g_ubias[BMAX * D];    // u@fg_user_W + fub + fib
__device__ float g_ugu[BMAX * LSEQ];   // u@instance_gate_user

static __device__ __forceinline__ u64 pk(float a, float b) {
    u64 r;
    asm("mov.b64 %0, {%1, %2};" : "=l"(r) : "f"(a), "f"(b));
    return r;
}
static __device__ __forceinline__ void upk(u64 v, float& a, float& b) {
    asm("mov.b64 {%0, %1}, %2;" : "=f"(a), "=f"(b) : "l"(v));
}
static __device__ __forceinline__ u64 fma2(u64 a, u64 b, u64 c) {
    u64 r;
    asm("fma.rn.f32x2 %0, %1, %2, %3;" : "=l"(r) : "l"(a), "l"(b), "l"(c));
    return r;
}
static __device__ __forceinline__ u64 add2(u64 a, u64 b) {
    u64 r;
    asm("add.rn.f32x2 %0, %1, %2;" : "=l"(r) : "l"(a), "l"(b));
    return r;
}
static __device__ __forceinline__ float sigmoidf(float x) {
    return 1.0f / (1.0f + __expf(-x));
}

// ---------------------------------------------------------------------------
// Precompute: g_ubias[b][d] = u@fg_user_W + fub + fib ; g_ugu[b][l] = u@gu
// ---------------------------------------------------------------------------
__global__ __launch_bounds__(128) void hgn_pre(
    const int* __restrict__ user_ids, const float* __restrict__ user_tab,
    const float* __restrict__ fuW, const float* __restrict__ fub,
    const float* __restrict__ fib, const float* __restrict__ gu, int B)
{
    __shared__ __align__(16) float s_u[D];
    const int j = threadIdx.x;
    float wcol[D];
    float biasj = 0.0f;
    if (j < D) {
        #pragma unroll
        for (int k = 0; k < D; k++) wcol[k] = fuW[k * D + j];
        biasj = fub[j] + fib[j];
    } else if (j < D + LSEQ) {
        const int jj = j - D;
        #pragma unroll
        for (int k = 0; k < D; k++) wcol[k] = gu[k * LSEQ + jj];
    }
    const int b0 = blockIdx.x * PRE_BPB;
    for (int bb = 0; bb < PRE_BPB; bb++) {
        const int b = b0 + bb;
        if (b >= B) break;
        if (j < D) s_u[j] = user_tab[(size_t)user_ids[b] * D + j];
        __syncthreads();
        float acc = biasj;
        const float4* up = (const float4*)s_u;
        #pragma unroll
        for (int q = 0; q < D / 4; q++) {
            float4 r = up[q];
            acc += r.x * wcol[4*q] + r.y * wcol[4*q+1] + r.z * wcol[4*q+2] + r.w * wcol[4*q+3];
        }
        if (j < D)             g_ubias[b * D + j] = acc;
        else if (j < D + LSEQ) g_ugu[b * LSEQ + (j - D)] = acc;
        __syncthreads();
    }
}

// ---------------------------------------------------------------------------
// Main kernel: one batch per 128-thread block, 4 warps = 4 K-quarters.
// R9 structure; occupancy raised from 8 -> 9 blocks/SM:
//   - __launch_bounds__(128, 9) -> 56-reg target (regfile: 9*128*56 <= 64K)
//   - subtile 13 -> 9 rows (s_pp 13.3KB -> 9.2KB; total smem ~23.9KB -> 24KB
//     alloc; 9*24 = 216KB <= 228KB carveout)
//   - scoring iter-0 register prefetch dropped (frees regs; extra resident
//     blocks now cover the union-phase latency instead)
// ---------------------------------------------------------------------------
__global__ __launch_bounds__(128, 9) void hgn_main(
    const int* __restrict__ item_seq,
    const int* __restrict__ user_ids,
    const int* __restrict__ items_pred,
    const float* __restrict__ user_tab,
    const float* __restrict__ item_tab,
    const float* __restrict__ fiW,
    const float* __restrict__ gi,
    const float* __restrict__ W2,
    const float* __restrict__ b2,
    float* __restrict__ out,
    int B)
{
    __shared__ __align__(16) float s_item[LSEQ][D];     // items -> gated (packed, in place)
    __shared__ __align__(16) u64 s_pp[4][SUBMAX][32];   // per-warp packed partials
    __shared__ __align__(16) u64 s_isump[4][32];        // per-warp packed item sums
    __shared__ __align__(16) float s_v[D];
    __shared__ float s_score[LSEQ];
    __shared__ int s_idx[TPRED];

    const int tid  = threadIdx.x;
    const int lane = tid & 31;
    const int w    = tid >> 5;       // warp = K-quarter
    const int b    = blockIdx.x;
    if (b >= B) return;

    // Packed weight quarter: colp[j] = (fiW[16w+j][lane], fiW[16w+j][lane+32])
    u64 colp[16];
    #pragma unroll
    for (int j = 0; j < 16; j++) {
        colp[j] = pk(fiW[(16 * w + j) * D + lane],
                     fiW[(16 * w + j) * D + lane + 32]);
    }
    const float gi_lo = gi[lane];
    const float gi_hi = gi[lane + 32];

    // --- gather item rows (16 threads share one seq index -> LDG bcast);
    //     stage prediction indices in the same phase ---
    #pragma unroll
    for (int i = 0; i < 7; i++) {
        const int idx = tid + 128 * i;
        if (idx < LSEQ * 16) {
            const int rl = idx >> 4, q = idx & 15;
            const int it = __ldg(&item_seq[(size_t)b * LSEQ + rl]);
            ((float4*)s_item[rl])[q] =
                ((const float4*)(item_tab + (size_t)it * D))[q];
        }
    }
    if (tid < TPRED) s_idx[tid] = items_pred[(size_t)b * TPRED + tid];
    const float biasA = g_ubias[b * D + lane];
    const float biasB = g_ubias[b * D + lane + 32];
    const float uemb  = (tid < D) ? user_tab[(size_t)user_ids[b] * D + tid] : 0.0f;
    __syncthreads();

    // --- gating GEMM + fused combine/instance-score, 6 row subtiles ---
    const int SUB0[7] = {0, 9, 18, 27, 36, 45, 50};
    u64 isum2 = pk(0.f, 0.f);
    #pragma unroll
    for (int s = 0; s < 6; s++) {
        const int l0 = SUB0[s], l1 = SUB0[s + 1];
        int l = l0;
        for (; l + 1 < l1; l += 2) {
            u64 a0 = pk(0.f, 0.f), a1 = pk(0.f, 0.f);
            u64 c0 = pk(0.f, 0.f), c1 = pk(0.f, 0.f);
            const float4* r0 = (const float4*)&s_item[l][16 * w];
            const float4* r1 = (const float4*)&s_item[l + 1][16 * w];
            #pragma unroll
            for (int q = 0; q < 4; q++) {
                const float4 x = r0[q];
                a0 = fma2(pk(x.x, x.x), colp[4*q+0], a0);
                a1 = fma2(pk(x.y, x.y), colp[4*q+1], a1);
                a0 = fma2(pk(x.z, x.z), colp[4*q+2], a0);
                a1 = fma2(pk(x.w, x.w), colp[4*q+3], a1);
                const float4 y = r1[q];
                c0 = fma2(pk(y.x, y.x), colp[4*q+0], c0);
                c1 = fma2(pk(y.y, y.y), colp[4*q+1], c1);
                c0 = fma2(pk(y.z, y.z), colp[4*q+2], c0);
                c1 = fma2(pk(y.w, y.w), colp[4*q+3], c1);
            }
            s_pp[w][l - l0][lane]     = add2(a0, a1);
            s_pp[w][l + 1 - l0][lane] = add2(c0, c1);
        }
        if (l < l1) {
            u64 a0 = pk(0.f, 0.f), a1 = pk(0.f, 0.f);
            const float4* r0 = (const float4*)&s_item[l][16 * w];
            #pragma unroll
            for (int q = 0; q < 4; q++) {
                const float4 x = r0[q];
                a0 = fma2(pk(x.x, x.x), colp[4*q+0], a0);
                a1 = fma2(pk(x.y, x.y), colp[4*q+1], a1);
                a0 = fma2(pk(x.z, x.z), colp[4*q+2], a0);
                a1 = fma2(pk(x.w, x.w), colp[4*q+3], a1);
            }
            s_pp[w][l - l0][lane] = add2(a0, a1);
        }
        __syncthreads();
        // combine + gate + instance score, rows strided over warps.
        for (int lc = l0 + w; lc < l1; lc += 4) {
            const float ug = g_ugu[b * LSEQ + lc];
            const float itA = s_item[lc][lane];
            const float itB = s_item[lc][lane + 32];
            const u64 p = add2(add2(s_pp[0][lc - l0][lane], s_pp[1][lc - l0][lane]),
                               add2(s_pp[2][lc - l0][lane], s_pp[3][lc - l0][lane]));
            float pA, pB;
            upk(p, pA, pB);
            const float gA = itA * sigmoidf(pA + biasA);
            const float gB = itB * sigmoidf(pB + biasB);
            isum2 = add2(isum2, pk(itA, itB));
            float sp = gA * gi_lo + gB * gi_hi;
            sp += __shfl_xor_sync(0xffffffffu, sp, 16);
            sp += __shfl_xor_sync(0xffffffffu, sp, 8);
            sp += __shfl_xor_sync(0xffffffffu, sp, 4);
            sp += __shfl_xor_sync(0xffffffffu, sp, 2);
            sp += __shfl_xor_sync(0xffffffffu, sp, 1);
            if (lane == 0) s_score[lc] = sigmoidf(sp + ug);
            ((float2*)s_item[lc])[lane] = make_float2(gA, gB);
        }
        __syncthreads();
    }
    s_isump[w][lane] = isum2;

    // --- union + v (64 threads) ---
    if (tid < D) {
        const int j = tid & 31, half = tid >> 5;
        float ssum = 0.0f, uo = 0.0f;
        #pragma unroll 5
        for (int l = 0; l < LSEQ; l++) {
            const float sc = s_score[l];
            ssum += sc;
            uo += s_item[l][2 * j + half] * sc;
        }
        const u64 is4 = add2(add2(s_isump[0][j], s_isump[1][j]),
                             add2(s_isump[2][j], s_isump[3][j]));
        float isA, isB;
        upk(is4, isA, isB);
        s_v[tid] = uemb + (half ? isB : isA) + uo / ssum;
    }
    __syncthreads();

    // --- scoring: 4 warps x 4 outputs/iter over 100 outputs ---
    {
        const int g4 = lane >> 3;
        const int gl = lane & 7;
        const float4 va = *(const float4*)&s_v[gl * 8];
        const float4 vb = *(const float4*)&s_v[gl * 8 + 4];
        float* outp = out + (size_t)b * TPRED;
        #pragma unroll
        for (int i = 0; i < 7; i++) {
            const int t = w * 4 + g4 + 16 * i;
            const int tt = (t < TPRED) ? t : 0;
            const int it = s_idx[tt];
            const float4* rowp = (const float4*)(W2 + (size_t)it * D);
            const float4 a = rowp[gl * 2];
            const float4 c = rowp[gl * 2 + 1];
            float p = a.x * va.x + a.y * va.y + a.z * va.z + a.w * va.w
                    + c.x * vb.x + c.y * vb.y + c.z * vb.z + c.w * vb.w;
            p += __shfl_xor_sync(0xffffffffu, p, 1);
            p += __shfl_xor_sync(0xffffffffu, p, 2);
            p += __shfl_xor_sync(0xffffffffu, p, 4);
            if (t < TPRED && gl == 0) outp[t] = p + b2[it];
        }
    }
}

// ---------------------------------------------------------------------------
// Harness entry. Inputs (metadata order):
//  0 item_seq[B,L] i32   1 user_ids[B] i32      2 items_to_predict[B,T] i32
//  3 user_emb[U,D] f32   4 item_emb[I,D] f32
//  5 fg_item_W[D,D]      6 fg_item_b[D]         7 fg_user_W[D,D]   8 fg_user_b[D]
//  9 instance_gate_item[D,1]  10 instance_gate_user[D,L]
// 11 W2_table[I,D]      12 b2_table[I,1]
// Output: res[B,T] f32
// ---------------------------------------------------------------------------
extern "C" void kernel_launch(void* const* d_in, const int* in_sizes, int n_in,
                              void* d_out, int out_size)
{
    const int*   item_seq   = (const int*)d_in[0];
    const int*   user_ids   = (const int*)d_in[1];
    const int*   items_pred = (const int*)d_in[2];
    const float* user_tab   = (const float*)d_in[3];
    const float* item_tab   = (const float*)d_in[4];
    const float* fiW        = (const float*)d_in[5];
    const float* fib        = (const float*)d_in[6];
    const float* fuW        = (const float*)d_in[7];
    const float* fub        = (const float*)d_in[8];
    const float* gi         = (const float*)d_in[9];
    const float* gu         = (const float*)d_in[10];
    const float* W2         = (const float*)d_in[11];
    const float* b2         = (const float*)d_in[12];
    float*       out        = (float*)d_out;

    const int B = in_sizes[1];

    const int pre_grid = (B + PRE_BPB - 1) / PRE_BPB;

    hgn_pre<<<pre_grid, 128>>>(user_ids, user_tab, fuW, fub, fib, gu, B);
    hgn_main<<<B, 128>>>(item_seq, user_ids, items_pred,
                         user_tab, item_tab, fiW, gi, W2, b2, out, B);
}

// round 15
// speedup vs baseline: 1.1995x; 1.1337x over previous
#include <cuda_runtime.h>
#include <cstdint>

// HGN forward. Shapes fixed: U=I=100000, D=64, L=50, B=4096, T=100.
#define D 64
#define LSEQ 50
#define TPRED 100
#define PRE_BPB 4
#define BMAX 4096
#define SUBMAX 13

typedef unsigned long long u64;

__device__ float g_ubias[BMAX * D];    // u@fg_user_W + fub + fib
__device__ float g_ugu[BMAX * LSEQ];   // u@instance_gate_user

static __device__ __forceinline__ u64 pk(float a, float b) {
    u64 r;
    asm("mov.b64 %0, {%1, %2};" : "=l"(r) : "f"(a), "f"(b));
    return r;
}
static __device__ __forceinline__ void upk(u64 v, float& a, float& b) {
    asm("mov.b64 {%0, %1}, %2;" : "=f"(a), "=f"(b) : "l"(v));
}
static __device__ __forceinline__ u64 fma2(u64 a, u64 b, u64 c) {
    u64 r;
    asm("fma.rn.f32x2 %0, %1, %2, %3;" : "=l"(r) : "l"(a), "l"(b), "l"(c));
    return r;
}
static __device__ __forceinline__ u64 add2(u64 a, u64 b) {
    u64 r;
    asm("add.rn.f32x2 %0, %1, %2;" : "=l"(r) : "l"(a), "l"(b));
    return r;
}
static __device__ __forceinline__ float sigmoidf(float x) {
    return 1.0f / (1.0f + __expf(-x));
}

// ---------------------------------------------------------------------------
// Precompute: g_ubias[b][d] = u@fg_user_W + fub + fib ; g_ugu[b][l] = u@gu
// ---------------------------------------------------------------------------
__global__ __launch_bounds__(128) void hgn_pre(
    const int* __restrict__ user_ids, const float* __restrict__ user_tab,
    const float* __restrict__ fuW, const float* __restrict__ fub,
    const float* __restrict__ fib, const float* __restrict__ gu, int B)
{
    __shared__ __align__(16) float s_u[D];
    const int j = threadIdx.x;
    float wcol[D];
    float biasj = 0.0f;
    if (j < D) {
        #pragma unroll
        for (int k = 0; k < D; k++) wcol[k] = fuW[k * D + j];
        biasj = fub[j] + fib[j];
    } else if (j < D + LSEQ) {
        const int jj = j - D;
        #pragma unroll
        for (int k = 0; k < D; k++) wcol[k] = gu[k * LSEQ + jj];
    }
    const int b0 = blockIdx.x * PRE_BPB;
    for (int bb = 0; bb < PRE_BPB; bb++) {
        const int b = b0 + bb;
        if (b >= B) break;
        if (j < D) s_u[j] = user_tab[(size_t)user_ids[b] * D + j];
        __syncthreads();
        float acc = biasj;
        const float4* up = (const float4*)s_u;
        #pragma unroll
        for (int q = 0; q < D / 4; q++) {
            float4 r = up[q];
            acc += r.x * wcol[4*q] + r.y * wcol[4*q+1] + r.z * wcol[4*q+2] + r.w * wcol[4*q+3];
        }
        if (j < D)             g_ubias[b * D + j] = acc;
        else if (j < D + LSEQ) g_ugu[b * LSEQ + (j - D)] = acc;
        __syncthreads();
    }
}

// ---------------------------------------------------------------------------
// Main kernel: one batch per 128-thread block, 4 warps = 4 K-quarters.
// Lane owns column pair (d=lane, d=lane+32); packed f32x2 weights in regs.
// Instance score fused into the combine pass. Gated values overwrite s_item
// rows packed: gated(d) at s_item[l][2*(d&31) + (d>>5)].
// R15 deltas vs R9: (a) no per-row __syncwarp in combine (program order
// covers same-thread same-address LDS->STS); (b) gated STS hoisted above the
// 5-SHFL reduction chain so publication isn't serialized behind it.
// Resource point held at regs=64 / smem=28KB / 8 blocks/SM (validated optimum).
// ---------------------------------------------------------------------------
__global__ __launch_bounds__(128, 8) void hgn_main(
    const int* __restrict__ item_seq,
    const int* __restrict__ user_ids,
    const int* __restrict__ items_pred,
    const float* __restrict__ user_tab,
    const float* __restrict__ item_tab,
    const float* __restrict__ fiW,
    const float* __restrict__ gi,
    const float* __restrict__ W2,
    const float* __restrict__ b2,
    float* __restrict__ out,
    int B)
{
    __shared__ __align__(16) float s_item[LSEQ][D];     // items -> gated (packed, in place)
    __shared__ __align__(16) u64 s_pp[4][SUBMAX][32];   // per-warp packed partials
    __shared__ __align__(16) u64 s_isump[4][32];        // per-warp packed item sums
    __shared__ __align__(16) float s_v[D];
    __shared__ float s_score[LSEQ];
    __shared__ int s_idx[TPRED];

    const int tid  = threadIdx.x;
    const int lane = tid & 31;
    const int w    = tid >> 5;       // warp = K-quarter
    const int b    = blockIdx.x;
    if (b >= B) return;

    // Packed weight quarter: colp[j] = (fiW[16w+j][lane], fiW[16w+j][lane+32])
    u64 colp[16];
    #pragma unroll
    for (int j = 0; j < 16; j++) {
        colp[j] = pk(fiW[(16 * w + j) * D + lane],
                     fiW[(16 * w + j) * D + lane + 32]);
    }
    const float gi_lo = gi[lane];
    const float gi_hi = gi[lane + 32];

    // --- gather item rows (16 threads share one seq index -> LDG bcast);
    //     stage prediction indices in the same phase ---
    #pragma unroll
    for (int i = 0; i < 7; i++) {
        const int idx = tid + 128 * i;
        if (idx < LSEQ * 16) {
            const int rl = idx >> 4, q = idx & 15;
            const int it = __ldg(&item_seq[(size_t)b * LSEQ + rl]);
            ((float4*)s_item[rl])[q] =
                ((const float4*)(item_tab + (size_t)it * D))[q];
        }
    }
    if (tid < TPRED) s_idx[tid] = items_pred[(size_t)b * TPRED + tid];
    const float biasA = g_ubias[b * D + lane];
    const float biasB = g_ubias[b * D + lane + 32];
    const float uemb  = (tid < D) ? user_tab[(size_t)user_ids[b] * D + tid] : 0.0f;
    __syncthreads();

    // --- gating GEMM + fused combine/instance-score, 4 row subtiles ---
    const int SUB0[5] = {0, 13, 26, 38, 50};
    u64 isum2 = pk(0.f, 0.f);
    #pragma unroll
    for (int s = 0; s < 4; s++) {
        const int l0 = SUB0[s], l1 = SUB0[s + 1];
        int l = l0;
        for (; l + 1 < l1; l += 2) {
            u64 a0 = pk(0.f, 0.f), a1 = pk(0.f, 0.f);
            u64 c0 = pk(0.f, 0.f), c1 = pk(0.f, 0.f);
            const float4* r0 = (const float4*)&s_item[l][16 * w];
            const float4* r1 = (const float4*)&s_item[l + 1][16 * w];
            #pragma unroll
            for (int q = 0; q < 4; q++) {
                const float4 x = r0[q];
                a0 = fma2(pk(x.x, x.x), colp[4*q+0], a0);
                a1 = fma2(pk(x.y, x.y), colp[4*q+1], a1);
                a0 = fma2(pk(x.z, x.z), colp[4*q+2], a0);
                a1 = fma2(pk(x.w, x.w), colp[4*q+3], a1);
                const float4 y = r1[q];
                c0 = fma2(pk(y.x, y.x), colp[4*q+0], c0);
                c1 = fma2(pk(y.y, y.y), colp[4*q+1], c1);
                c0 = fma2(pk(y.z, y.z), colp[4*q+2], c0);
                c1 = fma2(pk(y.w, y.w), colp[4*q+3], c1);
            }
            s_pp[w][l - l0][lane]     = add2(a0, a1);
            s_pp[w][l + 1 - l0][lane] = add2(c0, c1);
        }
        if (l < l1) {
            u64 a0 = pk(0.f, 0.f), a1 = pk(0.f, 0.f);
            const float4* r0 = (const float4*)&s_item[l][16 * w];
            #pragma unroll
            for (int q = 0; q < 4; q++) {
                const float4 x = r0[q];
                a0 = fma2(pk(x.x, x.x), colp[4*q+0], a0);
                a1 = fma2(pk(x.y, x.y), colp[4*q+1], a1);
                a0 = fma2(pk(x.z, x.z), colp[4*q+2], a0);
                a1 = fma2(pk(x.w, x.w), colp[4*q+3], a1);
            }
            s_pp[w][l - l0][lane] = add2(a0, a1);
        }
        __syncthreads();
        // combine + gate + instance score, rows strided over warps.
        // Gated pair is published (STS) BEFORE the shuffle chain; no syncwarp
        // needed (same-thread same-address LDS->STS is program-ordered, and
        // rows are warp-exclusive in this phase).
        for (int lc = l0 + w; lc < l1; lc += 4) {
            const float ug = g_ugu[b * LSEQ + lc];
            const float itA = s_item[lc][lane];
            const float itB = s_item[lc][lane + 32];
            const u64 p = add2(add2(s_pp[0][lc - l0][lane], s_pp[1][lc - l0][lane]),
                               add2(s_pp[2][lc - l0][lane], s_pp[3][lc - l0][lane]));
            float pA, pB;
            upk(p, pA, pB);
            const float gA = itA * sigmoidf(pA + biasA);
            const float gB = itB * sigmoidf(pB + biasB);
            ((float2*)s_item[lc])[lane] = make_float2(gA, gB);
            isum2 = add2(isum2, pk(itA, itB));
            float sp = gA * gi_lo + gB * gi_hi;
            sp += __shfl_xor_sync(0xffffffffu, sp, 16);
            sp += __shfl_xor_sync(0xffffffffu, sp, 8);
            sp += __shfl_xor_sync(0xffffffffu, sp, 4);
            sp += __shfl_xor_sync(0xffffffffu, sp, 2);
            sp += __shfl_xor_sync(0xffffffffu, sp, 1);
            if (lane == 0) s_score[lc] = sigmoidf(sp + ug);
        }
        __syncthreads();
    }
    s_isump[w][lane] = isum2;

    // --- prefetch scoring iter 0 (covers union latency) ---
    const int g4 = lane >> 3;
    const int gl = lane & 7;
    const int t0 = w * 4 + g4;
    const int it0 = s_idx[t0];
    const float4* row0 = (const float4*)(W2 + (size_t)it0 * D);
    const float4 pa = row0[gl * 2];
    const float4 pc = row0[gl * 2 + 1];
    const float pb2 = b2[it0];

    // --- union + v (64 threads) ---
    if (tid < D) {
        const int j = tid & 31, half = tid >> 5;
        float ssum = 0.0f, uo = 0.0f;
        #pragma unroll 5
        for (int l = 0; l < LSEQ; l++) {
            const float sc = s_score[l];
            ssum += sc;
            uo += s_item[l][2 * j + half] * sc;
        }
        const u64 is4 = add2(add2(s_isump[0][j], s_isump[1][j]),
                             add2(s_isump[2][j], s_isump[3][j]));
        float isA, isB;
        upk(is4, isA, isB);
        s_v[tid] = uemb + (half ? isB : isA) + uo / ssum;
    }
    __syncthreads();

    // --- scoring: 4 warps x 4 outputs/iter over 100 outputs ---
    {
        const float4 va = *(const float4*)&s_v[gl * 8];
        const float4 vb = *(const float4*)&s_v[gl * 8 + 4];
        float* outp = out + (size_t)b * TPRED;
        // iter 0 from prefetched registers
        {
            float p = pa.x * va.x + pa.y * va.y + pa.z * va.z + pa.w * va.w
                    + pc.x * vb.x + pc.y * vb.y + pc.z * vb.z + pc.w * vb.w;
            p += __shfl_xor_sync(0xffffffffu, p, 1);
            p += __shfl_xor_sync(0xffffffffu, p, 2);
            p += __shfl_xor_sync(0xffffffffu, p, 4);
            if (gl == 0) outp[t0] = p + pb2;
        }
        #pragma unroll
        for (int i = 1; i < 7; i++) {
            const int t = w * 4 + g4 + 16 * i;
            const int tt = (t < TPRED) ? t : 0;
            const int it = s_idx[tt];
            const float4* rowp = (const float4*)(W2 + (size_t)it * D);
            const float4 a = rowp[gl * 2];
            const float4 c = rowp[gl * 2 + 1];
            float p = a.x * va.x + a.y * va.y + a.z * va.z + a.w * va.w
                    + c.x * vb.x + c.y * vb.y + c.z * vb.z + c.w * vb.w;
            p += __shfl_xor_sync(0xffffffffu, p, 1);
            p += __shfl_xor_sync(0xffffffffu, p, 2);
            p += __shfl_xor_sync(0xffffffffu, p, 4);
            if (t < TPRED && gl == 0) outp[t] = p + b2[it];
        }
    }
}

// ---------------------------------------------------------------------------
// Harness entry. Inputs (metadata order):
//  0 item_seq[B,L] i32   1 user_ids[B] i32      2 items_to_predict[B,T] i32
//  3 user_emb[U,D] f32   4 item_emb[I,D] f32
//  5 fg_item_W[D,D]      6 fg_item_b[D]         7 fg_user_W[D,D]   8 fg_user_b[D]
//  9 instance_gate_item[D,1]  10 instance_gate_user[D,L]
// 11 W2_table[I,D]      12 b2_table[I,1]
// Output: res[B,T] f32
// ---------------------------------------------------------------------------
extern "C" void kernel_launch(void* const* d_in, const int* in_sizes, int n_in,
                              void* d_out, int out_size)
{
    const int*   item_seq   = (const int*)d_in[0];
    const int*   user_ids   = (const int*)d_in[1];
    const int*   items_pred = (const int*)d_in[2];
    const float* user_tab   = (const float*)d_in[3];
    const float* item_tab   = (const float*)d_in[4];
    const float* fiW        = (const float*)d_in[5];
    const float* fib        = (const float*)d_in[6];
    const float* fuW        = (const float*)d_in[7];
    const float* fub        = (const float*)d_in[8];
    const float* gi         = (const float*)d_in[9];
    const float* gu         = (const float*)d_in[10];
    const float* W2         = (const float*)d_in[11];
    const float* b2         = (const float*)d_in[12];
    float*       out        = (float*)d_out;

    const int B = in_sizes[1];

    const int pre_grid = (B + PRE_BPB - 1) / PRE_BPB;

    hgn_pre<<<pre_grid, 128>>>(user_ids, user_tab, fuW, fub, fib, gu, B);
    hgn_main<<<B, 128>>>(item_seq, user_ids, items_pred,
                         user_tab, item_tab, fiW, gi, W2, b2, out, B);
}

// round 17
// speedup vs baseline: 1.3782x; 1.1490x over previous
#include <cuda_runtime.h>
#include <cstdint>

// HGN forward. Shapes fixed: U=I=100000, D=64, L=50, B=4096, T=100.
#define D 64
#define LSEQ 50
#define TPRED 100
#define PRE_BPB 4
#define BMAX 4096
#define TSTR 73     // s_T row stride (floats): bank(k,l) = (9k+l)%32

__device__ float g_ubias[BMAX * D];    // u@fg_user_W + fub + fib
__device__ float g_ugu[BMAX * LSEQ];   // u@instance_gate_user

static __device__ __forceinline__ float sigmoidf(float x) {
    return 1.0f / (1.0f + __expf(-x));
}
static __device__ __forceinline__ uint32_t cvt_tf32(float f) {
    uint32_t u;
    asm("cvt.rna.tf32.f32 %0, %1;" : "=r"(u) : "f"(f));
    return u;
}
static __device__ __forceinline__ void mma_tf32(
    float& d0, float& d1, float& d2, float& d3,
    uint32_t a0, uint32_t a1, uint32_t a2, uint32_t a3,
    uint32_t b0, uint32_t b1)
{
    asm volatile(
        "mma.sync.aligned.m16n8k8.row.col.f32.tf32.tf32.f32 "
        "{%0,%1,%2,%3}, {%4,%5,%6,%7}, {%8,%9}, {%0,%1,%2,%3};"
        : "+f"(d0), "+f"(d1), "+f"(d2), "+f"(d3)
        : "r"(a0), "r"(a1), "r"(a2), "r"(a3), "r"(b0), "r"(b1));
}

// ---------------------------------------------------------------------------
// Precompute: g_ubias[b][d] = u@fg_user_W + fub + fib ; g_ugu[b][l] = u@gu
// ---------------------------------------------------------------------------
__global__ __launch_bounds__(128) void hgn_pre(
    const int* __restrict__ user_ids, const float* __restrict__ user_tab,
    const float* __restrict__ fuW, const float* __restrict__ fub,
    const float* __restrict__ fib, const float* __restrict__ gu, int B)
{
    __shared__ __align__(16) float s_u[D];
    const int j = threadIdx.x;
    float wcol[D];
    float biasj = 0.0f;
    if (j < D) {
        #pragma unroll
        for (int k = 0; k < D; k++) wcol[k] = fuW[k * D + j];
        biasj = fub[j] + fib[j];
    } else if (j < D + LSEQ) {
        const int jj = j - D;
        #pragma unroll
        for (int k = 0; k < D; k++) wcol[k] = gu[k * LSEQ + jj];
    }
    const int b0 = blockIdx.x * PRE_BPB;
    for (int bb = 0; bb < PRE_BPB; bb++) {
        const int b = b0 + bb;
        if (b >= B) break;
        if (j < D) s_u[j] = user_tab[(size_t)user_ids[b] * D + j];
        __syncthreads();
        float acc = biasj;
        const float4* up = (const float4*)s_u;
        #pragma unroll
        for (int q = 0; q < D / 4; q++) {
            float4 r = up[q];
            acc += r.x * wcol[4*q] + r.y * wcol[4*q+1] + r.z * wcol[4*q+2] + r.w * wcol[4*q+3];
        }
        if (j < D)             g_ubias[b * D + j] = acc;
        else if (j < D + LSEQ) g_ugu[b * LSEQ + (j - D)] = acc;
        __syncthreads();
    }
}

// ---------------------------------------------------------------------------
// Main kernel: one batch per 128-thread block, tensor-core gating GEMM.
// logitT[dout][l] = sum_k W[k][dout] * itemT[k][l]  via mma.sync m16n8k8 tf32.
// Warp w owns dout-stripe [16w,16w+16); full K=64; N=64 (l; 50 valid, tail
// garbage never consumed). Items live transposed in s_T[k][l] (stride 73);
// after a block barrier (all mma B-reads done) the epilogue overwrites s_T
// in place with gated values; union reads them row-contiguous per d.
// Bias folded into accumulator init. A operands cvt.rna tf32; B truncated.
// ---------------------------------------------------------------------------
__global__ __launch_bounds__(128, 8) void hgn_main(
    const int* __restrict__ item_seq,
    const int* __restrict__ user_ids,
    const int* __restrict__ items_pred,
    const float* __restrict__ user_tab,
    const float* __restrict__ item_tab,
    const float* __restrict__ fiW,
    const float* __restrict__ gi,
    const float* __restrict__ W2,
    const float* __restrict__ b2,
    float* __restrict__ out,
    int B)
{
    __shared__ __align__(16) float s_T[64 * TSTR];   // itemT -> gatedT (in place)
    __shared__ __align__(16) float s_scp[64][4];     // per-warp instance partials
    __shared__ float s_score[64];
    __shared__ float s_isum[64];
    __shared__ __align__(16) float s_v[D];
    __shared__ int s_idx[TPRED];

    const int tid  = threadIdx.x;
    const int lane = tid & 31;
    const int w    = tid >> 5;
    const int grp  = lane >> 2;      // 0..7
    const int t4   = lane & 3;       // 0..3
    const int m0   = 16 * w + grp;   // thread's dout rows: m0, m0+8
    const int b    = blockIdx.x;
    if (b >= B) return;

    // --- gather item rows, store TRANSPOSED: s_T[k][l] = item[l][k] ---
    #pragma unroll
    for (int i = 0; i < 7; i++) {
        const int idx = tid + 128 * i;
        if (idx < LSEQ * 16) {
            const int rl = idx >> 4, q = idx & 15;
            const int it = __ldg(&item_seq[(size_t)b * LSEQ + rl]);
            const float4 v = ((const float4*)(item_tab + (size_t)it * D))[q];
            s_T[(4 * q + 0) * TSTR + rl] = v.x;
            s_T[(4 * q + 1) * TSTR + rl] = v.y;
            s_T[(4 * q + 2) * TSTR + rl] = v.z;
            s_T[(4 * q + 3) * TSTR + rl] = v.w;
        }
    }
    if (tid < TPRED) s_idx[tid] = items_pred[(size_t)b * TPRED + tid];
    const float biasA = g_ubias[b * D + m0];
    const float biasB = g_ubias[b * D + m0 + 8];
    const float giA   = gi[m0];
    const float giB   = gi[m0 + 8];
    const float uemb  = (tid < D) ? user_tab[(size_t)user_ids[b] * D + tid] : 0.0f;
    __syncthreads();

    // --- mma mainloop: 8 k-tiles x 8 n-tiles; bias pre-folded into accs ---
    float acc[8][4];
    #pragma unroll
    for (int nt = 0; nt < 8; nt++) {
        acc[nt][0] = biasA; acc[nt][1] = biasA;
        acc[nt][2] = biasB; acc[nt][3] = biasB;
    }
    // A frags streamed from global (L2-hot), 1-deep prefetch
    uint32_t p0, p1, p2, p3;
    {
        const int k0 = t4, k1 = t4 + 4;
        p0 = cvt_tf32(fiW[k0 * D + m0]);
        p1 = cvt_tf32(fiW[k0 * D + m0 + 8]);
        p2 = cvt_tf32(fiW[k1 * D + m0]);
        p3 = cvt_tf32(fiW[k1 * D + m0 + 8]);
    }
    #pragma unroll
    for (int kt = 0; kt < 8; kt++) {
        const uint32_t a0 = p0, a1 = p1, a2 = p2, a3 = p3;
        if (kt < 7) {
            const int k0 = (kt + 1) * 8 + t4, k1 = k0 + 4;
            p0 = cvt_tf32(fiW[k0 * D + m0]);
            p1 = cvt_tf32(fiW[k0 * D + m0 + 8]);
            p2 = cvt_tf32(fiW[k1 * D + m0]);
            p3 = cvt_tf32(fiW[k1 * D + m0 + 8]);
        }
        const float* Bb = s_T + (kt * 8 + t4) * TSTR + grp;
        #pragma unroll
        for (int nt = 0; nt < 8; nt++) {
            const uint32_t b0 = __float_as_uint(Bb[nt * 8]);
            const uint32_t b1 = __float_as_uint(Bb[4 * TSTR + nt * 8]);
            mma_tf32(acc[nt][0], acc[nt][1], acc[nt][2], acc[nt][3],
                     a0, a1, a2, a3, b0, b1);
        }
    }
    __syncthreads();   // ALL B reads complete before gated overwrites s_T

    // --- epilogue: gate, in-place gated write, instance partials, isum ---
    float is0 = 0.0f, is8 = 0.0f;
    #pragma unroll
    for (int nt = 0; nt < 8; nt++) {
        const int l = nt * 8 + 2 * t4;
        float* r0 = s_T + m0 * TSTR + l;
        float* r8 = s_T + (m0 + 8) * TSTR + l;
        const float it00 = r0[0], it01 = r0[1];
        const float it10 = r8[0], it11 = r8[1];
        const float g00 = it00 * sigmoidf(acc[nt][0]);
        const float g01 = it01 * sigmoidf(acc[nt][1]);
        const float g10 = it10 * sigmoidf(acc[nt][2]);
        const float g11 = it11 * sigmoidf(acc[nt][3]);
        r0[0] = g00; r0[1] = g01; r8[0] = g10; r8[1] = g11;
        if (l < LSEQ)     { is0 += it00; is8 += it10; }
        if (l + 1 < LSEQ) { is0 += it01; is8 += it11; }
        float s0 = giA * g00 + giB * g10;
        float s1 = giA * g01 + giB * g11;
        s0 += __shfl_xor_sync(0xffffffffu, s0, 4);
        s1 += __shfl_xor_sync(0xffffffffu, s1, 4);
        s0 += __shfl_xor_sync(0xffffffffu, s0, 8);
        s1 += __shfl_xor_sync(0xffffffffu, s1, 8);
        s0 += __shfl_xor_sync(0xffffffffu, s0, 16);
        s1 += __shfl_xor_sync(0xffffffffu, s1, 16);
        if (grp == 0) { s_scp[l][w] = s0; s_scp[l + 1][w] = s1; }
    }
    is0 += __shfl_xor_sync(0xffffffffu, is0, 1);
    is8 += __shfl_xor_sync(0xffffffffu, is8, 1);
    is0 += __shfl_xor_sync(0xffffffffu, is0, 2);
    is8 += __shfl_xor_sync(0xffffffffu, is8, 2);
    if (t4 == 0) { s_isum[m0] = is0; s_isum[m0 + 8] = is8; }
    __syncthreads();

    // --- finalize instance scores ---
    if (tid < LSEQ) {
        const float4 sp = *(const float4*)s_scp[tid];
        s_score[tid] = sigmoidf(sp.x + sp.y + sp.z + sp.w + g_ugu[b * LSEQ + tid]);
    }
    __syncthreads();

    // --- prefetch scoring iter 0 (covers union latency) ---
    const int g4 = lane >> 3;
    const int gl = lane & 7;
    const int t0 = w * 4 + g4;
    const int it0 = s_idx[t0];
    const float4* row0 = (const float4*)(W2 + (size_t)it0 * D);
    const float4 pa = row0[gl * 2];
    const float4 pc = row0[gl * 2 + 1];
    const float pb2 = b2[it0];

    // --- union + v (64 threads; gated rows are l-contiguous, conflict-free) ---
    if (tid < D) {
        const float* gp = s_T + tid * TSTR;
        float ssum = 0.0f, uo = 0.0f;
        #pragma unroll 5
        for (int l = 0; l < LSEQ; l++) {
            const float sc = s_score[l];
            ssum += sc;
            uo += gp[l] * sc;
        }
        s_v[tid] = uemb + s_isum[tid] + uo / ssum;
    }
    __syncthreads();

    // --- scoring: 4 warps x 4 outputs/iter over 100 outputs ---
    {
        const float4 va = *(const float4*)&s_v[gl * 8];
        const float4 vb = *(const float4*)&s_v[gl * 8 + 4];
        float* outp = out + (size_t)b * TPRED;
        {
            float p = pa.x * va.x + pa.y * va.y + pa.z * va.z + pa.w * va.w
                    + pc.x * vb.x + pc.y * vb.y + pc.z * vb.z + pc.w * vb.w;
            p += __shfl_xor_sync(0xffffffffu, p, 1);
            p += __shfl_xor_sync(0xffffffffu, p, 2);
            p += __shfl_xor_sync(0xffffffffu, p, 4);
            if (gl == 0) outp[t0] = p + pb2;
        }
        #pragma unroll
        for (int i = 1; i < 7; i++) {
            const int t = w * 4 + g4 + 16 * i;
            const int tt = (t < TPRED) ? t : 0;
            const int it = s_idx[tt];
            const float4* rowp = (const float4*)(W2 + (size_t)it * D);
            const float4 a = rowp[gl * 2];
            const float4 c = rowp[gl * 2 + 1];
            float p = a.x * va.x + a.y * va.y + a.z * va.z + a.w * va.w
                    + c.x * vb.x + c.y * vb.y + c.z * vb.z + c.w * vb.w;
            p += __shfl_xor_sync(0xffffffffu, p, 1);
            p += __shfl_xor_sync(0xffffffffu, p, 2);
            p += __shfl_xor_sync(0xffffffffu, p, 4);
            if (t < TPRED && gl == 0) outp[t] = p + b2[it];
        }
    }
}

// ---------------------------------------------------------------------------
// Harness entry. Inputs (metadata order):
//  0 item_seq[B,L] i32   1 user_ids[B] i32      2 items_to_predict[B,T] i32
//  3 user_emb[U,D] f32   4 item_emb[I,D] f32
//  5 fg_item_W[D,D]      6 fg_item_b[D]         7 fg_user_W[D,D]   8 fg_user_b[D]
//  9 instance_gate_item[D,1]  10 instance_gate_user[D,L]
// 11 W2_table[I,D]      12 b2_table[I,1]
// Output: res[B,T] f32
// ---------------------------------------------------------------------------
extern "C" void kernel_launch(void* const* d_in, const int* in_sizes, int n_in,
                              void* d_out, int out_size)
{
    const int*   item_seq   = (const int*)d_in[0];
    const int*   user_ids   = (const int*)d_in[1];
    const int*   items_pred = (const int*)d_in[2];
    const float* user_tab   = (const float*)d_in[3];
    const float* item_tab   = (const float*)d_in[4];
    const float* fiW        = (const float*)d_in[5];
    const float* fib        = (const float*)d_in[6];
    const float* fuW        = (const float*)d_in[7];
    const float* fub        = (const float*)d_in[8];
    const float* gi         = (const float*)d_in[9];
    const float* gu         = (const float*)d_in[10];
    const float* W2         = (const float*)d_in[11];
    const float* b2         = (const float*)d_in[12];
    float*       out        = (float*)d_out;

    const int B = in_sizes[1];

    const int pre_grid = (B + PRE_BPB - 1) / PRE_BPB;

    hgn_pre<<<pre_grid, 128>>>(user_ids, user_tab, fuW, fub, fib, gu, B);
    hgn_main<<<B, 128>>>(item_seq, user_ids, items_pred,
                         user_tab, item_tab, fiW, gi, W2, b2, out, B);
}